// round 4
// baseline (speedup 1.0000x reference)
#include <cuda_runtime.h>
#include <math.h>

// ---------------- problem constants ----------------
#define Bsz   16
#define Nseq  784
#define DIM   512
#define Hh    8
#define KDIM  64
#define VDIM  256
#define RESW  28
#define QKVO  3072      // (2*64+256)*8
#define Mrows (Bsz*Nseq) // 12544
#define EPSV  1e-5f
#define SCALEV 0.125f    // 64^-0.5

// ---------------- scratch (device globals; no allocs allowed) ----------------
// Q, K stored TRANSPOSED per (b,h):  [bh][d][n]
__device__ float g_Q[(size_t)Bsz*Hh*KDIM*Nseq];
__device__ float g_K[(size_t)Bsz*Hh*KDIM*Nseq];
__device__ float g_V[(size_t)Bsz*Hh*Nseq*VDIM];
__device__ float g_AO[(size_t)Bsz*Nseq*Hh*VDIM];

// =====================================================================
// GEMM 1: qkv = BN(x @ qkv_w^T) -> scatter to Q^T/K^T/V
// 128x128 tile, BK=16, 256 thr, 8x8 microtile (split 4+4 rows/cols),
// double-buffered smem (1 sync per k-tile).
// =====================================================================
__global__ __launch_bounds__(256) void gemm_qkv_kernel(
    const float* __restrict__ A, const float* __restrict__ W,
    const float* __restrict__ gamma, const float* __restrict__ beta,
    const float* __restrict__ mean, const float* __restrict__ var)
{
    __shared__ float As[2][16][132];
    __shared__ float Ws[2][16][132];
    const int K = DIM;
    const int bm = blockIdx.x * 128;
    const int bn = blockIdx.y * 128;
    const int tid = threadIdx.x;
    const int a0 = (tid >> 4) << 2;      // rows a0..a0+3 and a0+64..a0+67
    const int b0 = (tid & 15) << 2;      // cols b0..b0+3 and b0+64..b0+67
    const int lrow = tid >> 2;           // 0..63 (plus +64 second load)
    const int lk4  = (tid & 3) << 2;

    float acc[8][8];
#pragma unroll
    for (int i = 0; i < 8; i++)
#pragma unroll
        for (int j = 0; j < 8; j++) acc[i][j] = 0.f;

    // initial tile -> buffer 0
    {
        float4 av0 = *(const float4*)(A + (size_t)(bm + lrow) * K + lk4);
        float4 av1 = *(const float4*)(A + (size_t)(bm + lrow + 64) * K + lk4);
        float4 wv0 = *(const float4*)(W + (size_t)(bn + lrow) * K + lk4);
        float4 wv1 = *(const float4*)(W + (size_t)(bn + lrow + 64) * K + lk4);
        As[0][lk4+0][lrow] = av0.x; As[0][lk4+1][lrow] = av0.y;
        As[0][lk4+2][lrow] = av0.z; As[0][lk4+3][lrow] = av0.w;
        As[0][lk4+0][lrow+64] = av1.x; As[0][lk4+1][lrow+64] = av1.y;
        As[0][lk4+2][lrow+64] = av1.z; As[0][lk4+3][lrow+64] = av1.w;
        Ws[0][lk4+0][lrow] = wv0.x; Ws[0][lk4+1][lrow] = wv0.y;
        Ws[0][lk4+2][lrow] = wv0.z; Ws[0][lk4+3][lrow] = wv0.w;
        Ws[0][lk4+0][lrow+64] = wv1.x; Ws[0][lk4+1][lrow+64] = wv1.y;
        Ws[0][lk4+2][lrow+64] = wv1.z; Ws[0][lk4+3][lrow+64] = wv1.w;
    }
    __syncthreads();

    int p = 0;
    for (int k0 = 0; k0 < K; k0 += 16) {
        const bool more = (k0 + 16 < K);
        float4 av0, av1, wv0, wv1;
        if (more) {
            av0 = *(const float4*)(A + (size_t)(bm + lrow) * K + k0 + 16 + lk4);
            av1 = *(const float4*)(A + (size_t)(bm + lrow + 64) * K + k0 + 16 + lk4);
            wv0 = *(const float4*)(W + (size_t)(bn + lrow) * K + k0 + 16 + lk4);
            wv1 = *(const float4*)(W + (size_t)(bn + lrow + 64) * K + k0 + 16 + lk4);
        }
#pragma unroll
        for (int k = 0; k < 16; k++) {
            float4 al = *(const float4*)&As[p][k][a0];
            float4 ah = *(const float4*)&As[p][k][a0 + 64];
            float4 bl = *(const float4*)&Ws[p][k][b0];
            float4 bh = *(const float4*)&Ws[p][k][b0 + 64];
            float aa[8] = {al.x, al.y, al.z, al.w, ah.x, ah.y, ah.z, ah.w};
            float bb[8] = {bl.x, bl.y, bl.z, bl.w, bh.x, bh.y, bh.z, bh.w};
#pragma unroll
            for (int i = 0; i < 8; i++)
#pragma unroll
                for (int j = 0; j < 8; j++)
                    acc[i][j] += aa[i] * bb[j];
        }
        if (more) {
            int q = p ^ 1;
            As[q][lk4+0][lrow] = av0.x; As[q][lk4+1][lrow] = av0.y;
            As[q][lk4+2][lrow] = av0.z; As[q][lk4+3][lrow] = av0.w;
            As[q][lk4+0][lrow+64] = av1.x; As[q][lk4+1][lrow+64] = av1.y;
            As[q][lk4+2][lrow+64] = av1.z; As[q][lk4+3][lrow+64] = av1.w;
            Ws[q][lk4+0][lrow] = wv0.x; Ws[q][lk4+1][lrow] = wv0.y;
            Ws[q][lk4+2][lrow] = wv0.z; Ws[q][lk4+3][lrow] = wv0.w;
            Ws[q][lk4+0][lrow+64] = wv1.x; Ws[q][lk4+1][lrow+64] = wv1.y;
            Ws[q][lk4+2][lrow+64] = wv1.z; Ws[q][lk4+3][lrow+64] = wv1.w;
            __syncthreads();
        }
        p ^= 1;
    }

#pragma unroll
    for (int jj = 0; jj < 8; jj++) {
        int col = bn + ((jj < 4) ? (b0 + jj) : (64 + b0 + jj - 4));
        float sc = gamma[col] * rsqrtf(var[col] + EPSV);
        float sh = beta[col] - mean[col] * sc;
        int h  = col / 384;
        int rr = col - h * 384;
#pragma unroll
        for (int ii = 0; ii < 8; ii++) {
            int row = bm + ((ii < 4) ? (a0 + ii) : (64 + a0 + ii - 4));
            int b = row / Nseq;
            int n = row - b * Nseq;
            float val = acc[ii][jj] * sc + sh;
            int bh = b * Hh + h;
            if (rr < KDIM)
                g_Q[((size_t)bh * KDIM + rr) * Nseq + n] = val;
            else if (rr < 2 * KDIM)
                g_K[((size_t)bh * KDIM + (rr - KDIM)) * Nseq + n] = val;
            else
                g_V[((size_t)bh * Nseq + n) * VDIM + (rr - 2 * KDIM)] = val;
        }
    }
}

// =====================================================================
// Attention v3: PV stage restructured to float4 P loads (12 LDS.128 per
// 128 FFMA). CTA: 256 thr, 64 q rows, key tiles of 64, V chunked 2x128.
// smem = 88896 B.
// =====================================================================
#define ATT_SMEM 88896
__global__ __launch_bounds__(256, 2) void attn_kernel(const float* __restrict__ biases)
{
    extern __shared__ float smem[];
    float (*Qst)[68]  = (float(*)[68])smem;                 // [64 d][64 rows+pad]
    float (*Kst)[68]  = (float(*)[68])(smem + 4352);        // [64 d][64 keys+pad]
    float (*Ps)[68]   = (float(*)[68])(smem + 8704);        // [64 rows][64 keys+pad]
    float (*Vs)[128]  = (float(*)[128])(smem + 13056);      // [64 keys][128 vcols]
    float* brow = smem + 21248;                             // 784
    float* marr = smem + 22032;                             // 64
    float* larr = smem + 22096;                             // 64
    float* carr = smem + 22160;                             // 64

    const int bh = blockIdx.y;          // b*8+h
    const int b  = bh >> 3;
    const int h  = bh & 7;
    const int n0 = blockIdx.x * 64;
    const int tid  = threadIdx.x;
    const int lane = tid & 31;
    const int w    = tid >> 5;

    const float* Qb = g_Q + (size_t)bh * KDIM * Nseq;
    const float* Kb = g_K + (size_t)bh * KDIM * Nseq;
    const float* Vb = g_V + (size_t)bh * Nseq * VDIM;

    for (int i = tid; i < Nseq; i += 256) brow[i] = biases[h * Nseq + i];
    if (tid < 64) { marr[tid] = -1e30f; larr[tid] = 0.f; }

    // load Q^T tile (64 d x 64 rows)
#pragma unroll
    for (int i = 0; i < 4; i++) {
        int s  = tid + i * 256;
        int d  = s >> 4;
        int q4 = (s & 15) << 2;
        float4 v = (n0 + q4 < Nseq)
                 ? *(const float4*)(Qb + (size_t)d * Nseq + n0 + q4)
                 : make_float4(0.f, 0.f, 0.f, 0.f);
        *(float4*)&Qst[d][q4] = v;
    }

    const int sr = (tid >> 4) << 2;
    const int sc = (tid & 15) << 2;
    const int ro = w << 3;
    const int co = lane << 2;

    int ry[4], rx[4];
#pragma unroll
    for (int i = 0; i < 4; i++) {
        int n = n0 + sr + i;
        int nc = (n < Nseq) ? n : (Nseq - 1);
        ry[i] = nc / RESW;
        rx[i] = nc - ry[i] * RESW;
    }

    float o[8][8];
#pragma unroll
    for (int i = 0; i < 8; i++)
#pragma unroll
        for (int j = 0; j < 8; j++) o[i][j] = 0.f;

    const int NTILE = (Nseq + 63) / 64;   // 13
    for (int kt = 0; kt < NTILE; kt++) {
        const int mbase = kt * 64;
        __syncthreads();

        // load K^T tile (64 d x 64 keys)
#pragma unroll
        for (int i = 0; i < 4; i++) {
            int s  = tid + i * 256;
            int d  = s >> 4;
            int q4 = (s & 15) << 2;
            float4 v = (mbase + q4 < Nseq)
                     ? *(const float4*)(Kb + (size_t)d * Nseq + mbase + q4)
                     : make_float4(0.f, 0.f, 0.f, 0.f);
            *(float4*)&Kst[d][q4] = v;
        }
        __syncthreads();

        // ---- S = Q.K^T (4x4 microtile) ----
        float s4[4][4];
#pragma unroll
        for (int i = 0; i < 4; i++)
#pragma unroll
            for (int j = 0; j < 4; j++) s4[i][j] = 0.f;
#pragma unroll
        for (int d = 0; d < KDIM; d++) {
            float4 qv = *(const float4*)&Qst[d][sr];
            float4 kv = *(const float4*)&Kst[d][sc];
            float qa[4] = {qv.x, qv.y, qv.z, qv.w};
            float ka[4] = {kv.x, kv.y, kv.z, kv.w};
#pragma unroll
            for (int i = 0; i < 4; i++)
#pragma unroll
                for (int j = 0; j < 4; j++)
                    s4[i][j] += qa[i] * ka[j];
        }

        // bias + mask
        int myv[4], mxv[4];
        bool mval[4];
#pragma unroll
        for (int j = 0; j < 4; j++) {
            int m = mbase + sc + j;
            mval[j] = (m < Nseq);
            int mc = mval[j] ? m : (Nseq - 1);
            myv[j] = mc / RESW;
            mxv[j] = mc - myv[j] * RESW;
        }
#pragma unroll
        for (int i = 0; i < 4; i++)
#pragma unroll
            for (int j = 0; j < 4; j++) {
                int dy = abs(ry[i] - myv[j]);
                int dx = abs(rx[i] - mxv[j]);
                s4[i][j] = mval[j] ? (s4[i][j] * SCALEV + brow[dy * RESW + dx])
                                   : -1e30f;
            }

        // ---- online softmax ----
#pragma unroll
        for (int i = 0; i < 4; i++) {
            int r = sr + i;
            float tmax = fmaxf(fmaxf(s4[i][0], s4[i][1]), fmaxf(s4[i][2], s4[i][3]));
#pragma unroll
            for (int off = 8; off; off >>= 1)
                tmax = fmaxf(tmax, __shfl_xor_sync(0xffffffffu, tmax, off));
            float mold = marr[r];
            float mnew = fmaxf(mold, tmax);
            float4 pv;
            pv.x = __expf(s4[i][0] - mnew);
            pv.y = __expf(s4[i][1] - mnew);
            pv.z = __expf(s4[i][2] - mnew);
            pv.w = __expf(s4[i][3] - mnew);
            *(float4*)&Ps[r][sc] = pv;
            float psum = pv.x + pv.y + pv.z + pv.w;
#pragma unroll
            for (int off = 8; off; off >>= 1)
                psum += __shfl_xor_sync(0xffffffffu, psum, off);
            if ((tid & 15) == 0) {
                float corr = __expf(mold - mnew);
                larr[r] = larr[r] * corr + psum;
                marr[r] = mnew;
                carr[r] = corr;
            }
        }
        __syncthreads();

        // rescale O by row correction
#pragma unroll
        for (int i = 0; i < 8; i++) {
            float corr = carr[ro + i];
#pragma unroll
            for (int j = 0; j < 8; j++) o[i][j] *= corr;
        }

        // ---- PV over 2 vcol chunks of 128; keys 4 at a time ----
#pragma unroll
        for (int c = 0; c < 2; c++) {
#pragma unroll
            for (int i = 0; i < 8; i++) {
                int s  = tid + i * 256;
                int mm = s >> 5;
                int c4 = (s & 31) << 2;
                float4 v = (mbase + mm < Nseq)
                         ? *(const float4*)(Vb + (size_t)(mbase + mm) * VDIM + c * 128 + c4)
                         : make_float4(0.f, 0.f, 0.f, 0.f);
                *(float4*)&Vs[mm][c4] = v;
            }
            __syncthreads();

            const int c4o = c * 4;
#pragma unroll 2
            for (int mm0 = 0; mm0 < 64; mm0 += 4) {
                float4 v0 = *(const float4*)&Vs[mm0 + 0][co];
                float4 v1 = *(const float4*)&Vs[mm0 + 1][co];
                float4 v2 = *(const float4*)&Vs[mm0 + 2][co];
                float4 v3 = *(const float4*)&Vs[mm0 + 3][co];
#pragma unroll
                for (int i = 0; i < 8; i++) {
                    float4 p4 = *(const float4*)&Ps[ro + i][mm0];   // warp broadcast
                    o[i][c4o + 0] += p4.x * v0.x + p4.y * v1.x + p4.z * v2.x + p4.w * v3.x;
                    o[i][c4o + 1] += p4.x * v0.y + p4.y * v1.y + p4.z * v2.y + p4.w * v3.y;
                    o[i][c4o + 2] += p4.x * v0.z + p4.y * v1.z + p4.z * v2.z + p4.w * v3.z;
                    o[i][c4o + 3] += p4.x * v0.w + p4.y * v1.w + p4.z * v2.w + p4.w * v3.w;
                }
            }
            __syncthreads();
        }
    }

    // ---- epilogue: normalize, SiLU, store ----
#pragma unroll
    for (int i = 0; i < 8; i++) {
        int n = n0 + ro + i;
        if (n < Nseq) {
            float inv = 1.f / larr[ro + i];
            size_t base = ((size_t)b * Nseq + n) * (Hh * VDIM) + h * VDIM;
            float4 v0, v1;
            float t;
            t = o[i][0] * inv; v0.x = t / (1.f + __expf(-t));
            t = o[i][1] * inv; v0.y = t / (1.f + __expf(-t));
            t = o[i][2] * inv; v0.z = t / (1.f + __expf(-t));
            t = o[i][3] * inv; v0.w = t / (1.f + __expf(-t));
            t = o[i][4] * inv; v1.x = t / (1.f + __expf(-t));
            t = o[i][5] * inv; v1.y = t / (1.f + __expf(-t));
            t = o[i][6] * inv; v1.z = t / (1.f + __expf(-t));
            t = o[i][7] * inv; v1.w = t / (1.f + __expf(-t));
            *(float4*)(g_AO + base + co)       = v0;
            *(float4*)(g_AO + base + 128 + co) = v1;
        }
    }
}

// =====================================================================
// GEMM 2: out = BN(silu_out @ proj_w^T); M=12544, N=512, K=2048
// same structure as GEMM 1 (double-buffered, split fragments)
// =====================================================================
__global__ __launch_bounds__(256) void gemm_proj_kernel(
    const float* __restrict__ W,
    const float* __restrict__ gamma, const float* __restrict__ beta,
    const float* __restrict__ mean, const float* __restrict__ var,
    float* __restrict__ out)
{
    __shared__ float As[2][16][132];
    __shared__ float Ws[2][16][132];
    const int K = Hh * VDIM;   // 2048
    const float* A = g_AO;
    const int bm = blockIdx.x * 128;
    const int bn = blockIdx.y * 128;
    const int tid = threadIdx.x;
    const int a0 = (tid >> 4) << 2;
    const int b0 = (tid & 15) << 2;
    const int lrow = tid >> 2;
    const int lk4  = (tid & 3) << 2;

    float acc[8][8];
#pragma unroll
    for (int i = 0; i < 8; i++)
#pragma unroll
        for (int j = 0; j < 8; j++) acc[i][j] = 0.f;

    {
        float4 av0 = *(const float4*)(A + (size_t)(bm + lrow) * K + lk4);
        float4 av1 = *(const float4*)(A + (size_t)(bm + lrow + 64) * K + lk4);
        float4 wv0 = *(const float4*)(W + (size_t)(bn + lrow) * K + lk4);
        float4 wv1 = *(const float4*)(W + (size_t)(bn + lrow + 64) * K + lk4);
        As[0][lk4+0][lrow] = av0.x; As[0][lk4+1][lrow] = av0.y;
        As[0][lk4+2][lrow] = av0.z; As[0][lk4+3][lrow] = av0.w;
        As[0][lk4+0][lrow+64] = av1.x; As[0][lk4+1][lrow+64] = av1.y;
        As[0][lk4+2][lrow+64] = av1.z; As[0][lk4+3][lrow+64] = av1.w;
        Ws[0][lk4+0][lrow] = wv0.x; Ws[0][lk4+1][lrow] = wv0.y;
        Ws[0][lk4+2][lrow] = wv0.z; Ws[0][lk4+3][lrow] = wv0.w;
        Ws[0][lk4+0][lrow+64] = wv1.x; Ws[0][lk4+1][lrow+64] = wv1.y;
        Ws[0][lk4+2][lrow+64] = wv1.z; Ws[0][lk4+3][lrow+64] = wv1.w;
    }
    __syncthreads();

    int p = 0;
    for (int k0 = 0; k0 < K; k0 += 16) {
        const bool more = (k0 + 16 < K);
        float4 av0, av1, wv0, wv1;
        if (more) {
            av0 = *(const float4*)(A + (size_t)(bm + lrow) * K + k0 + 16 + lk4);
            av1 = *(const float4*)(A + (size_t)(bm + lrow + 64) * K + k0 + 16 + lk4);
            wv0 = *(const float4*)(W + (size_t)(bn + lrow) * K + k0 + 16 + lk4);
            wv1 = *(const float4*)(W + (size_t)(bn + lrow + 64) * K + k0 + 16 + lk4);
        }
#pragma unroll
        for (int k = 0; k < 16; k++) {
            float4 al = *(const float4*)&As[p][k][a0];
            float4 ah = *(const float4*)&As[p][k][a0 + 64];
            float4 bl = *(const float4*)&Ws[p][k][b0];
            float4 bh = *(const float4*)&Ws[p][k][b0 + 64];
            float aa[8] = {al.x, al.y, al.z, al.w, ah.x, ah.y, ah.z, ah.w};
            float bb[8] = {bl.x, bl.y, bl.z, bl.w, bh.x, bh.y, bh.z, bh.w};
#pragma unroll
            for (int i = 0; i < 8; i++)
#pragma unroll
                for (int j = 0; j < 8; j++)
                    acc[i][j] += aa[i] * bb[j];
        }
        if (more) {
            int q = p ^ 1;
            As[q][lk4+0][lrow] = av0.x; As[q][lk4+1][lrow] = av0.y;
            As[q][lk4+2][lrow] = av0.z; As[q][lk4+3][lrow] = av0.w;
            As[q][lk4+0][lrow+64] = av1.x; As[q][lk4+1][lrow+64] = av1.y;
            As[q][lk4+2][lrow+64] = av1.z; As[q][lk4+3][lrow+64] = av1.w;
            Ws[q][lk4+0][lrow] = wv0.x; Ws[q][lk4+1][lrow] = wv0.y;
            Ws[q][lk4+2][lrow] = wv0.z; Ws[q][lk4+3][lrow] = wv0.w;
            Ws[q][lk4+0][lrow+64] = wv1.x; Ws[q][lk4+1][lrow+64] = wv1.y;
            Ws[q][lk4+2][lrow+64] = wv1.z; Ws[q][lk4+3][lrow+64] = wv1.w;
            __syncthreads();
        }
        p ^= 1;
    }

#pragma unroll
    for (int jj = 0; jj < 8; jj++) {
        int col = bn + ((jj < 4) ? (b0 + jj) : (64 + b0 + jj - 4));
        float sc = gamma[col] * rsqrtf(var[col] + EPSV);
        float sh = beta[col] - mean[col] * sc;
#pragma unroll
        for (int ii = 0; ii < 8; ii++) {
            int row = bm + ((ii < 4) ? (a0 + ii) : (64 + a0 + ii - 4));
            out[(size_t)row * DIM + col] = acc[ii][jj] * sc + sh;
        }
    }
}

// =====================================================================
extern "C" void kernel_launch(void* const* d_in, const int* in_sizes, int n_in,
                              void* d_out, int out_size)
{
    const float* x          = (const float*)d_in[0];
    const float* qkv_w      = (const float*)d_in[1];
    const float* qkv_gamma  = (const float*)d_in[2];
    const float* qkv_beta   = (const float*)d_in[3];
    const float* qkv_mean   = (const float*)d_in[4];
    const float* qkv_var    = (const float*)d_in[5];
    const float* att_bias   = (const float*)d_in[6];
    const float* proj_w     = (const float*)d_in[7];
    const float* proj_gamma = (const float*)d_in[8];
    const float* proj_beta  = (const float*)d_in[9];
    const float* proj_mean  = (const float*)d_in[10];
    const float* proj_var   = (const float*)d_in[11];
    // d_in[12] = bias_idxs: computed analytically in-kernel

    cudaFuncSetAttribute(attn_kernel,
                         cudaFuncAttributeMaxDynamicSharedMemorySize, ATT_SMEM);

    gemm_qkv_kernel<<<dim3(Mrows / 128, QKVO / 128), 256>>>(
        x, qkv_w, qkv_gamma, qkv_beta, qkv_mean, qkv_var);

    attn_kernel<<<dim3((Nseq + 63) / 64, Bsz * Hh), 256, ATT_SMEM>>>(att_bias);

    gemm_proj_kernel<<<dim3(Mrows / 128, DIM / 128), 256>>>(
        proj_w, proj_gamma, proj_beta, proj_mean, proj_var, (float*)d_out);
}

// round 5
// speedup vs baseline: 1.6293x; 1.6293x over previous
#include <cuda_runtime.h>
#include <mma.h>
#include <math.h>

using namespace nvcuda;

// ---------------- problem constants ----------------
#define Bsz   16
#define Nseq  784
#define DIM   512
#define Hh    8
#define KDIM  64
#define VDIM  256
#define RESW  28
#define QKVO  3072      // (2*64+256)*8
#define Mrows (Bsz*Nseq) // 12544
#define EPSV  1e-5f
#define SCALEV 0.125f    // 64^-0.5
#define LDA   36        // smem row stride (floats) for GEMM tiles

// ---------------- scratch (device globals; no allocs allowed) ----------------
// Q, K stored TRANSPOSED per (b,h):  [bh][d][n]
__device__ float g_Q[(size_t)Bsz*Hh*KDIM*Nseq];
__device__ float g_K[(size_t)Bsz*Hh*KDIM*Nseq];
__device__ float g_V[(size_t)Bsz*Hh*Nseq*VDIM];
__device__ float g_AO[(size_t)Bsz*Nseq*Hh*VDIM];

// =====================================================================
// GEMM 1 (TF32 WMMA): qkv = BN(x @ qkv_w^T) -> scatter to Q^T/K^T/V
// CTA tile 128x128, BK=32, 8 warps * (32x64), m16n16k8 tf32 frags.
// =====================================================================
__global__ __launch_bounds__(256) void gemm_qkv_kernel(
    const float* __restrict__ A, const float* __restrict__ W,
    const float* __restrict__ gamma, const float* __restrict__ beta,
    const float* __restrict__ mean, const float* __restrict__ var)
{
    __shared__ float As[128][LDA];
    __shared__ float Bs[128][LDA];
    __shared__ float stage[8][16 * 20];

    const int K  = DIM;
    const int bm = blockIdx.x * 128;
    const int bn = blockIdx.y * 128;
    const int tid  = threadIdx.x;
    const int wid  = tid >> 5;
    const int lane = tid & 31;
    const int wm = wid & 3;      // warp row block: rows wm*32..+31
    const int wn = wid >> 2;     // warp col block: cols wn*64..+63

    wmma::fragment<wmma::accumulator, 16, 16, 8, float> cf[2][4];
#pragma unroll
    for (int mi = 0; mi < 2; mi++)
#pragma unroll
        for (int ni = 0; ni < 4; ni++)
            wmma::fill_fragment(cf[mi][ni], 0.f);

    for (int k0 = 0; k0 < K; k0 += 32) {
        __syncthreads();
#pragma unroll
        for (int i = 0; i < 4; i++) {
            int s   = tid + i * 256;
            int row = s >> 3;
            int c4  = (s & 7) << 2;
            float4 av = *(const float4*)(A + (size_t)(bm + row) * K + k0 + c4);
            float4 wv = *(const float4*)(W + (size_t)(bn + row) * K + k0 + c4);
            // round to tf32 at store time
            As[row][c4+0] = wmma::__float_to_tf32(av.x);
            As[row][c4+1] = wmma::__float_to_tf32(av.y);
            As[row][c4+2] = wmma::__float_to_tf32(av.z);
            As[row][c4+3] = wmma::__float_to_tf32(av.w);
            Bs[row][c4+0] = wmma::__float_to_tf32(wv.x);
            Bs[row][c4+1] = wmma::__float_to_tf32(wv.y);
            Bs[row][c4+2] = wmma::__float_to_tf32(wv.z);
            Bs[row][c4+3] = wmma::__float_to_tf32(wv.w);
        }
        __syncthreads();

#pragma unroll
        for (int kk = 0; kk < 32; kk += 8) {
            wmma::fragment<wmma::matrix_b, 16, 16, 8, wmma::precision::tf32, wmma::col_major> bf[4];
#pragma unroll
            for (int ni = 0; ni < 4; ni++)
                wmma::load_matrix_sync(bf[ni], &Bs[wn * 64 + ni * 16][kk], LDA);
#pragma unroll
            for (int mi = 0; mi < 2; mi++) {
                wmma::fragment<wmma::matrix_a, 16, 16, 8, wmma::precision::tf32, wmma::row_major> af;
                wmma::load_matrix_sync(af, &As[wm * 32 + mi * 16][kk], LDA);
#pragma unroll
                for (int ni = 0; ni < 4; ni++)
                    wmma::mma_sync(cf[mi][ni], af, bf[ni], cf[mi][ni]);
            }
        }
    }

    // ---- epilogue: stage per-warp, BN, scatter to Q^T/K^T/V ----
    float* st = &stage[wid][0];
    const int r0 = lane >> 3;          // 0..3
    const int c0 = (lane & 7) << 1;    // 0,2,..14
#pragma unroll
    for (int mi = 0; mi < 2; mi++)
#pragma unroll
        for (int ni = 0; ni < 4; ni++) {
            wmma::store_matrix_sync(st, cf[mi][ni], 20, wmma::mem_row_major);
            __syncwarp();
#pragma unroll
            for (int rr = 0; rr < 4; rr++) {
                int r = r0 + rr * 4;
                int row = bm + wm * 32 + mi * 16 + r;
                int b = row / Nseq;
                int n = row - b * Nseq;
#pragma unroll
                for (int cc = 0; cc < 2; cc++) {
                    int c = c0 + cc;
                    int col = bn + wn * 64 + ni * 16 + c;
                    float sc = gamma[col] * rsqrtf(var[col] + EPSV);
                    float sh = beta[col] - mean[col] * sc;
                    float val = st[r * 20 + c] * sc + sh;
                    int h  = col / 384;
                    int rrv = col - h * 384;
                    int bh = b * Hh + h;
                    if (rrv < KDIM)
                        g_Q[((size_t)bh * KDIM + rrv) * Nseq + n] = val;
                    else if (rrv < 2 * KDIM)
                        g_K[((size_t)bh * KDIM + (rrv - KDIM)) * Nseq + n] = val;
                    else
                        g_V[((size_t)bh * Nseq + n) * VDIM + (rrv - 2 * KDIM)] = val;
                }
            }
            __syncwarp();
        }
}

// =====================================================================
// Attention (round-3 verified version, unchanged): flash-style fp32.
// CTA: 256 thr, 64 q rows, key tiles of 64, V chunked 2x128.
// =====================================================================
#define ATT_SMEM 88896
__global__ __launch_bounds__(256, 2) void attn_kernel(const float* __restrict__ biases)
{
    extern __shared__ float smem[];
    float (*Qst)[68]  = (float(*)[68])smem;                 // [64 d][64 rows+pad]
    float (*Kst)[68]  = (float(*)[68])(smem + 4352);        // [64 d][64 keys+pad]
    float (*Ps)[68]   = (float(*)[68])(smem + 8704);        // [64 rows][64 keys+pad]
    float (*Vs)[128]  = (float(*)[128])(smem + 13056);      // [64 keys][128 vcols]
    float* brow = smem + 21248;                             // 784
    float* marr = smem + 22032;                             // 64
    float* larr = smem + 22096;                             // 64
    float* carr = smem + 22160;                             // 64

    const int bh = blockIdx.y;          // b*8+h
    const int b  = bh >> 3;
    const int h  = bh & 7;
    const int n0 = blockIdx.x * 64;
    const int tid  = threadIdx.x;
    const int lane = tid & 31;
    const int w    = tid >> 5;

    const float* Qb = g_Q + (size_t)bh * KDIM * Nseq;
    const float* Kb = g_K + (size_t)bh * KDIM * Nseq;
    const float* Vb = g_V + (size_t)bh * Nseq * VDIM;

    for (int i = tid; i < Nseq; i += 256) brow[i] = biases[h * Nseq + i];
    if (tid < 64) { marr[tid] = -1e30f; larr[tid] = 0.f; }

    // load Q^T tile (64 d x 64 rows)
#pragma unroll
    for (int i = 0; i < 4; i++) {
        int s  = tid + i * 256;
        int d  = s >> 4;
        int q4 = (s & 15) << 2;
        float4 v = (n0 + q4 < Nseq)
                 ? *(const float4*)(Qb + (size_t)d * Nseq + n0 + q4)
                 : make_float4(0.f, 0.f, 0.f, 0.f);
        *(float4*)&Qst[d][q4] = v;
    }

    const int sr = (tid >> 4) << 2;
    const int sc = (tid & 15) << 2;
    const int ro = w << 3;
    const int co = lane << 2;

    int ry[4], rx[4];
#pragma unroll
    for (int i = 0; i < 4; i++) {
        int n = n0 + sr + i;
        int nc = (n < Nseq) ? n : (Nseq - 1);
        ry[i] = nc / RESW;
        rx[i] = nc - ry[i] * RESW;
    }

    float o[8][8];
#pragma unroll
    for (int i = 0; i < 8; i++)
#pragma unroll
        for (int j = 0; j < 8; j++) o[i][j] = 0.f;

    const int NTILE = (Nseq + 63) / 64;   // 13
    for (int kt = 0; kt < NTILE; kt++) {
        const int mbase = kt * 64;
        __syncthreads();

        // load K^T tile (64 d x 64 keys)
#pragma unroll
        for (int i = 0; i < 4; i++) {
            int s  = tid + i * 256;
            int d  = s >> 4;
            int q4 = (s & 15) << 2;
            float4 v = (mbase + q4 < Nseq)
                     ? *(const float4*)(Kb + (size_t)d * Nseq + mbase + q4)
                     : make_float4(0.f, 0.f, 0.f, 0.f);
            *(float4*)&Kst[d][q4] = v;
        }
        __syncthreads();

        // ---- S = Q.K^T (4x4 microtile) ----
        float s4[4][4];
#pragma unroll
        for (int i = 0; i < 4; i++)
#pragma unroll
            for (int j = 0; j < 4; j++) s4[i][j] = 0.f;
#pragma unroll
        for (int d = 0; d < KDIM; d++) {
            float4 qv = *(const float4*)&Qst[d][sr];
            float4 kv = *(const float4*)&Kst[d][sc];
            float qa[4] = {qv.x, qv.y, qv.z, qv.w};
            float ka[4] = {kv.x, kv.y, kv.z, kv.w};
#pragma unroll
            for (int i = 0; i < 4; i++)
#pragma unroll
                for (int j = 0; j < 4; j++)
                    s4[i][j] += qa[i] * ka[j];
        }

        // bias + mask
        int myv[4], mxv[4];
        bool mval[4];
#pragma unroll
        for (int j = 0; j < 4; j++) {
            int m = mbase + sc + j;
            mval[j] = (m < Nseq);
            int mc = mval[j] ? m : (Nseq - 1);
            myv[j] = mc / RESW;
            mxv[j] = mc - myv[j] * RESW;
        }
#pragma unroll
        for (int i = 0; i < 4; i++)
#pragma unroll
            for (int j = 0; j < 4; j++) {
                int dy = abs(ry[i] - myv[j]);
                int dx = abs(rx[i] - mxv[j]);
                s4[i][j] = mval[j] ? (s4[i][j] * SCALEV + brow[dy * RESW + dx])
                                   : -1e30f;
            }

        // ---- online softmax ----
#pragma unroll
        for (int i = 0; i < 4; i++) {
            int r = sr + i;
            float tmax = fmaxf(fmaxf(s4[i][0], s4[i][1]), fmaxf(s4[i][2], s4[i][3]));
#pragma unroll
            for (int off = 8; off; off >>= 1)
                tmax = fmaxf(tmax, __shfl_xor_sync(0xffffffffu, tmax, off));
            float mold = marr[r];
            float mnew = fmaxf(mold, tmax);
            float psum = 0.f;
#pragma unroll
            for (int j = 0; j < 4; j++) {
                float p = __expf(s4[i][j] - mnew);
                Ps[r][sc + j] = p;
                psum += p;
            }
#pragma unroll
            for (int off = 8; off; off >>= 1)
                psum += __shfl_xor_sync(0xffffffffu, psum, off);
            if ((tid & 15) == 0) {
                float corr = __expf(mold - mnew);
                larr[r] = larr[r] * corr + psum;
                marr[r] = mnew;
                carr[r] = corr;
            }
        }
        __syncthreads();

        // rescale O by row correction
#pragma unroll
        for (int i = 0; i < 8; i++) {
            float corr = carr[ro + i];
#pragma unroll
            for (int j = 0; j < 8; j++) o[i][j] *= corr;
        }

        // ---- PV over 2 vcol chunks of 128 ----
#pragma unroll
        for (int c = 0; c < 2; c++) {
#pragma unroll
            for (int i = 0; i < 8; i++) {
                int s  = tid + i * 256;
                int mm = s >> 5;
                int c4 = (s & 31) << 2;
                float4 v = (mbase + mm < Nseq)
                         ? *(const float4*)(Vb + (size_t)(mbase + mm) * VDIM + c * 128 + c4)
                         : make_float4(0.f, 0.f, 0.f, 0.f);
                *(float4*)&Vs[mm][c4] = v;
            }
            __syncthreads();

#pragma unroll 4
            for (int mm = 0; mm < 64; mm++) {
                float4 vv = *(const float4*)&Vs[mm][co];
                float va[4] = {vv.x, vv.y, vv.z, vv.w};
#pragma unroll
                for (int i = 0; i < 8; i++) {
                    float p = Ps[ro + i][mm];       // warp broadcast
#pragma unroll
                    for (int j = 0; j < 4; j++)
                        o[i][c * 4 + j] += p * va[j];
                }
            }
            __syncthreads();
        }
    }

    // ---- epilogue: normalize, SiLU, store ----
#pragma unroll
    for (int i = 0; i < 8; i++) {
        int n = n0 + ro + i;
        if (n < Nseq) {
            float inv = 1.f / larr[ro + i];
            size_t base = ((size_t)b * Nseq + n) * (Hh * VDIM) + h * VDIM;
            float4 v0, v1;
            float t;
            t = o[i][0] * inv; v0.x = t / (1.f + __expf(-t));
            t = o[i][1] * inv; v0.y = t / (1.f + __expf(-t));
            t = o[i][2] * inv; v0.z = t / (1.f + __expf(-t));
            t = o[i][3] * inv; v0.w = t / (1.f + __expf(-t));
            t = o[i][4] * inv; v1.x = t / (1.f + __expf(-t));
            t = o[i][5] * inv; v1.y = t / (1.f + __expf(-t));
            t = o[i][6] * inv; v1.z = t / (1.f + __expf(-t));
            t = o[i][7] * inv; v1.w = t / (1.f + __expf(-t));
            *(float4*)(g_AO + base + co)       = v0;
            *(float4*)(g_AO + base + 128 + co) = v1;
        }
    }
}

// =====================================================================
// GEMM 2 (TF32 WMMA): out = BN(silu_out @ proj_w^T); M=12544,N=512,K=2048
// =====================================================================
__global__ __launch_bounds__(256) void gemm_proj_kernel(
    const float* __restrict__ W,
    const float* __restrict__ gamma, const float* __restrict__ beta,
    const float* __restrict__ mean, const float* __restrict__ var,
    float* __restrict__ out)
{
    __shared__ float As[128][LDA];
    __shared__ float Bs[128][LDA];
    __shared__ float stage[8][16 * 20];

    const int K  = Hh * VDIM;   // 2048
    const float* A = g_AO;
    const int bm = blockIdx.x * 128;
    const int bn = blockIdx.y * 128;
    const int tid  = threadIdx.x;
    const int wid  = tid >> 5;
    const int lane = tid & 31;
    const int wm = wid & 3;
    const int wn = wid >> 2;

    wmma::fragment<wmma::accumulator, 16, 16, 8, float> cf[2][4];
#pragma unroll
    for (int mi = 0; mi < 2; mi++)
#pragma unroll
        for (int ni = 0; ni < 4; ni++)
            wmma::fill_fragment(cf[mi][ni], 0.f);

    for (int k0 = 0; k0 < K; k0 += 32) {
        __syncthreads();
#pragma unroll
        for (int i = 0; i < 4; i++) {
            int s   = tid + i * 256;
            int row = s >> 3;
            int c4  = (s & 7) << 2;
            float4 av = *(const float4*)(A + (size_t)(bm + row) * K + k0 + c4);
            float4 wv = *(const float4*)(W + (size_t)(bn + row) * K + k0 + c4);
            As[row][c4+0] = wmma::__float_to_tf32(av.x);
            As[row][c4+1] = wmma::__float_to_tf32(av.y);
            As[row][c4+2] = wmma::__float_to_tf32(av.z);
            As[row][c4+3] = wmma::__float_to_tf32(av.w);
            Bs[row][c4+0] = wmma::__float_to_tf32(wv.x);
            Bs[row][c4+1] = wmma::__float_to_tf32(wv.y);
            Bs[row][c4+2] = wmma::__float_to_tf32(wv.z);
            Bs[row][c4+3] = wmma::__float_to_tf32(wv.w);
        }
        __syncthreads();

#pragma unroll
        for (int kk = 0; kk < 32; kk += 8) {
            wmma::fragment<wmma::matrix_b, 16, 16, 8, wmma::precision::tf32, wmma::col_major> bf[4];
#pragma unroll
            for (int ni = 0; ni < 4; ni++)
                wmma::load_matrix_sync(bf[ni], &Bs[wn * 64 + ni * 16][kk], LDA);
#pragma unroll
            for (int mi = 0; mi < 2; mi++) {
                wmma::fragment<wmma::matrix_a, 16, 16, 8, wmma::precision::tf32, wmma::row_major> af;
                wmma::load_matrix_sync(af, &As[wm * 32 + mi * 16][kk], LDA);
#pragma unroll
                for (int ni = 0; ni < 4; ni++)
                    wmma::mma_sync(cf[mi][ni], af, bf[ni], cf[mi][ni]);
            }
        }
    }

    // ---- epilogue: stage per-warp, BN, store ----
    float* st = &stage[wid][0];
    const int r0 = lane >> 3;
    const int c0 = (lane & 7) << 1;
#pragma unroll
    for (int mi = 0; mi < 2; mi++)
#pragma unroll
        for (int ni = 0; ni < 4; ni++) {
            wmma::store_matrix_sync(st, cf[mi][ni], 20, wmma::mem_row_major);
            __syncwarp();
#pragma unroll
            for (int rr = 0; rr < 4; rr++) {
                int r = r0 + rr * 4;
                int row = bm + wm * 32 + mi * 16 + r;
#pragma unroll
                for (int cc = 0; cc < 2; cc++) {
                    int c = c0 + cc;
                    int col = bn + wn * 64 + ni * 16 + c;
                    float sc = gamma[col] * rsqrtf(var[col] + EPSV);
                    float sh = beta[col] - mean[col] * sc;
                    out[(size_t)row * DIM + col] = st[r * 20 + c] * sc + sh;
                }
            }
            __syncwarp();
        }
}

// =====================================================================
extern "C" void kernel_launch(void* const* d_in, const int* in_sizes, int n_in,
                              void* d_out, int out_size)
{
    const float* x          = (const float*)d_in[0];
    const float* qkv_w      = (const float*)d_in[1];
    const float* qkv_gamma  = (const float*)d_in[2];
    const float* qkv_beta   = (const float*)d_in[3];
    const float* qkv_mean   = (const float*)d_in[4];
    const float* qkv_var    = (const float*)d_in[5];
    const float* att_bias   = (const float*)d_in[6];
    const float* proj_w     = (const float*)d_in[7];
    const float* proj_gamma = (const float*)d_in[8];
    const float* proj_beta  = (const float*)d_in[9];
    const float* proj_mean  = (const float*)d_in[10];
    const float* proj_var   = (const float*)d_in[11];
    // d_in[12] = bias_idxs: computed analytically in-kernel

    cudaFuncSetAttribute(attn_kernel,
                         cudaFuncAttributeMaxDynamicSharedMemorySize, ATT_SMEM);

    gemm_qkv_kernel<<<dim3(Mrows / 128, QKVO / 128), 256>>>(
        x, qkv_w, qkv_gamma, qkv_beta, qkv_mean, qkv_var);

    attn_kernel<<<dim3((Nseq + 63) / 64, Bsz * Hh), 256, ATT_SMEM>>>(att_bias);

    gemm_proj_kernel<<<dim3(Mrows / 128, DIM / 128), 256>>>(
        proj_w, proj_gamma, proj_beta, proj_mean, proj_var, (float*)d_out);
}